// round 3
// baseline (speedup 1.0000x reference)
#include <cuda_runtime.h>
#include <cuda_bf16.h>
#include <math.h>

// Problem constants (fixed by the reference)
#define NN 50000
#define HH 256
#define TT 4
#define LL 2
#define SS 3
#define CC 3
#define H3 (3 * HH)
#define THX (TT * HH)   // 1024

// ---------------- scratch: ONE device global, carved by offsets -------------
// (float units)
#define OFF_H    ((size_t)0)                       // [NN*HH]           node state
#define OFF_WH   (OFF_H    + (size_t)NN * HH)      // [NN*THX]          per-etype transforms
#define OFF_A    (OFF_WH   + (size_t)NN * THX)     // [NN*HH]           aggregated messages
#define OFF_GX   (OFF_A    + (size_t)NN * HH)      // [NN*H3]           a @ w_ih.T
#define OFF_WT   (OFF_GX   + (size_t)NN * H3)      // [LL*HH*THX]       W_lin transposed
#define OFF_WIT  (OFF_WT   + (size_t)LL * HH * THX)// [LL*HH*H3]        w_ih transposed
#define OFF_WHT  (OFF_WIT  + (size_t)LL * HH * H3) // [LL*HH*H3]        w_hh transposed
#define OFF_POOL (OFF_WHT  + (size_t)LL * HH * H3) // [HH]
#define SCRATCH_FLOATS (OFF_POOL + HH)
// gh aliases the Wh buffer: Wh is dead after the scatter, gh is produced after.

__device__ float s_scratch[SCRATCH_FLOATS];

// ---------------- generic helpers ----------------
__global__ void copy_kernel(const float* __restrict__ in, float* __restrict__ out, size_t n4) {
    size_t i = (size_t)blockIdx.x * blockDim.x + threadIdx.x;
    if (i < n4) ((float4*)out)[i] = ((const float4*)in)[i];
}

__global__ void zero_kernel(float* __restrict__ p, size_t n4) {
    size_t i = (size_t)blockIdx.x * blockDim.x + threadIdx.x;
    if (i < n4) ((float4*)p)[i] = make_float4(0.f, 0.f, 0.f, 0.f);
}

// in [rows, cols] -> out [cols, rows]
__global__ void transpose_kernel(const float* __restrict__ in, float* __restrict__ out,
                                 int rows, int cols) {
    int idx = blockIdx.x * blockDim.x + threadIdx.x;
    int total = rows * cols;
    if (idx >= total) return;
    int r = idx / cols;
    int c = idx - r * cols;
    out[(size_t)c * rows + r] = in[idx];
}

// ---------------- SGEMM: C[M,Nc] = A[M,K] @ B[K,Nc] + bias[Nc] ----------------
// 128x128 tile, BK=8, 256 threads, 8x8 per-thread register tile.
#define BM 128
#define BN 128
#define BK 8
#define TM 8
#define TN 8

__global__ __launch_bounds__(256, 2)
void sgemm_kernel(const float* __restrict__ A, const float* __restrict__ B,
                  const float* __restrict__ bias, float* __restrict__ C,
                  int M, int Nc, int K) {
    __shared__ float As[BK][BM];
    __shared__ float Bs[BK][BN];

    int tid = threadIdx.x;
    int block_row = blockIdx.y * BM;
    int block_col = blockIdx.x * BN;

    int a_row  = tid >> 1;          // 0..127
    int a_col4 = (tid & 1) * 4;     // 0 or 4
    int b_row = tid >> 5;           // 0..7
    int b_col = (tid & 31) * 4;     // 0..124

    int trow = (tid >> 4) * TM;     // 0..120
    int tcol = (tid & 15) * TN;     // 0..120

    float acc[TM][TN];
#pragma unroll
    for (int i = 0; i < TM; i++)
#pragma unroll
        for (int j = 0; j < TN; j++) acc[i][j] = 0.f;

    for (int k0 = 0; k0 < K; k0 += BK) {
        int gm = block_row + a_row;
        float4 av = make_float4(0.f, 0.f, 0.f, 0.f);
        if (gm < M) av = *(const float4*)&A[(size_t)gm * K + k0 + a_col4];
        As[a_col4 + 0][a_row] = av.x;
        As[a_col4 + 1][a_row] = av.y;
        As[a_col4 + 2][a_row] = av.z;
        As[a_col4 + 3][a_row] = av.w;

        float4 bv = *(const float4*)&B[(size_t)(k0 + b_row) * Nc + block_col + b_col];
        *(float4*)&Bs[b_row][b_col] = bv;

        __syncthreads();

#pragma unroll
        for (int kk = 0; kk < BK; kk++) {
            float a_frag[TM], b_frag[TN];
#pragma unroll
            for (int i = 0; i < TM; i++) a_frag[i] = As[kk][trow + i];
#pragma unroll
            for (int j = 0; j < TN; j++) b_frag[j] = Bs[kk][tcol + j];
#pragma unroll
            for (int i = 0; i < TM; i++)
#pragma unroll
                for (int j = 0; j < TN; j++)
                    acc[i][j] = fmaf(a_frag[i], b_frag[j], acc[i][j]);
        }
        __syncthreads();
    }

#pragma unroll
    for (int i = 0; i < TM; i++) {
        int gm = block_row + trow + i;
        if (gm >= M) continue;
#pragma unroll
        for (int j = 0; j < TN; j += 4) {
            int gc = block_col + tcol + j;
            float4 v;
            v.x = acc[i][j + 0] + bias[gc + 0];
            v.y = acc[i][j + 1] + bias[gc + 1];
            v.z = acc[i][j + 2] + bias[gc + 2];
            v.w = acc[i][j + 3] + bias[gc + 3];
            *(float4*)&C[(size_t)gm * Nc + gc] = v;
        }
    }
}

// ---------------- edge scatter: a[dst] += Wh[src, etype] ----------------
// one warp per edge; 2x float4 red.global per lane (8 floats each)
__global__ void scatter_kernel(const float* __restrict__ Wh,
                               const int* __restrict__ src,
                               const int* __restrict__ dst,
                               const int* __restrict__ et,
                               float* __restrict__ a, int E) {
    int gwarp = (int)(((size_t)blockIdx.x * blockDim.x + threadIdx.x) >> 5);
    int lane = threadIdx.x & 31;
    if (gwarp >= E) return;
    int s = __ldg(&src[gwarp]);
    int d = __ldg(&dst[gwarp]);
    int t = __ldg(&et[gwarp]);
    const float4* sp = (const float4*)(Wh + (size_t)s * THX + (size_t)t * HH);
    float4* dp = (float4*)(a + (size_t)d * HH);
#pragma unroll
    for (int i = 0; i < 2; i++) {
        float4 v = sp[lane + 32 * i];
        asm volatile("red.global.add.v4.f32 [%0], {%1,%2,%3,%4};"
                     :: "l"(dp + lane + 32 * i), "f"(v.x), "f"(v.y), "f"(v.z), "f"(v.w)
                     : "memory");
    }
}

// ---------------- GRU gates (elementwise, float4-vectorized) ----------------
__global__ void gru_kernel(const float4* __restrict__ gx, const float4* __restrict__ gh,
                           float4* __restrict__ h, int total4) {
    int idx = blockIdx.x * blockDim.x + threadIdx.x;
    if (idx >= total4) return;
    int n = idx >> 6;        // H/4 = 64 float4 per row
    int k = idx & 63;
    const float4* gxr = gx + (size_t)n * 192;  // 768/4
    const float4* ghr = gh + (size_t)n * 192;
    float4 xr = gxr[k], xz = gxr[64 + k], xn = gxr[128 + k];
    float4 hr = ghr[k], hz = ghr[64 + k], hn = ghr[128 + k];
    float4 hv = h[idx];
    float4 out;
#define GRU1(c)                                                       \
    {                                                                 \
        float r = 1.f / (1.f + expf(-(xr.c + hr.c)));                 \
        float z = 1.f / (1.f + expf(-(xz.c + hz.c)));                 \
        float nng = tanhf(xn.c + r * hn.c);                           \
        out.c = (1.f - z) * nng + z * hv.c;                           \
    }
    GRU1(x) GRU1(y) GRU1(z) GRU1(w)
#undef GRU1
    h[idx] = out;
}

// ---------------- pooling + FC ----------------
__global__ void pool_kernel(const float* __restrict__ h, float* __restrict__ pooled, int n) {
    int k = threadIdx.x;  // 256
    float acc = 0.f;
    for (int r = blockIdx.x; r < n; r += gridDim.x)
        acc += h[(size_t)r * HH + k];
    atomicAdd(&pooled[k], acc);
}

__global__ void fc_kernel(const float* __restrict__ pooled, const float* __restrict__ fc_w,
                          const float* __restrict__ fc_b, float* __restrict__ out, float invN) {
    int c = blockIdx.x;
    int lane = threadIdx.x;
    float acc = 0.f;
    for (int k = lane; k < HH; k += 32) acc += pooled[k] * fc_w[c * HH + k];
#pragma unroll
    for (int o = 16; o; o >>= 1) acc += __shfl_xor_sync(0xffffffffu, acc, o);
    if (lane == 0) out[c] = acc * invN + fc_b[c];
}

// ---------------- host orchestration ----------------
extern "C" void kernel_launch(void* const* d_in, const int* in_sizes, int n_in,
                              void* d_out, int out_size) {
    const float* x      = (const float*)d_in[0];
    const int*   src    = (const int*)d_in[1];
    const int*   dst    = (const int*)d_in[2];
    const int*   etype  = (const int*)d_in[3];
    const float* W_lin  = (const float*)d_in[4];   // [L,T,H,H]
    const float* b_lin  = (const float*)d_in[5];   // [L,T,H]
    const float* w_ih   = (const float*)d_in[6];   // [L,3H,H]
    const float* w_hh   = (const float*)d_in[7];   // [L,3H,H]
    const float* b_ih   = (const float*)d_in[8];   // [L,3H]
    const float* b_hh   = (const float*)d_in[9];   // [L,3H]
    const float* fc_w   = (const float*)d_in[10];  // [C,H]
    const float* fc_b   = (const float*)d_in[11];  // [C]
    float* out = (float*)d_out;

    const int E = in_sizes[1];

    float* base = nullptr;
    cudaGetSymbolAddress((void**)&base, s_scratch);
    float* p_h      = base + OFF_H;
    float* p_Wh     = base + OFF_WH;
    float* p_gh     = base + OFF_WH;   // alias: Wh dead after scatter, gh made after
    float* p_a      = base + OFF_A;
    float* p_gx     = base + OFF_GX;
    float* p_WT     = base + OFF_WT;
    float* p_wiT    = base + OFF_WIT;
    float* p_whT    = base + OFF_WHT;
    float* p_pooled = base + OFF_POOL;

    // ---- weight transposes (once per launch) ----
    {
        int totW = THX * HH;    // 1024*256 per layer
        int totG = H3 * HH;     // 768*256 per layer
        for (int l = 0; l < LL; l++) {
            transpose_kernel<<<(totW + 255) / 256, 256>>>(
                W_lin + (size_t)l * totW, p_WT + (size_t)l * totW, THX, HH);
            transpose_kernel<<<(totG + 255) / 256, 256>>>(
                w_ih + (size_t)l * totG, p_wiT + (size_t)l * totG, H3, HH);
            transpose_kernel<<<(totG + 255) / 256, 256>>>(
                w_hh + (size_t)l * totG, p_whT + (size_t)l * totG, H3, HH);
        }
    }

    // ---- h = x ----
    {
        size_t n4 = (size_t)NN * HH / 4;
        copy_kernel<<<(int)((n4 + 255) / 256), 256>>>(x, p_h, n4);
    }

    dim3 grid_wh((THX + BN - 1) / BN, (NN + BM - 1) / BM);   // (8, 391)
    dim3 grid_g((H3 + BN - 1) / BN, (NN + BM - 1) / BM);     // (6, 391)
    int scatter_blocks = (int)(((size_t)E * 32 + 255) / 256);
    size_t a4 = (size_t)NN * HH / 4;
    int gru_blocks = (int)((a4 + 255) / 256);

    for (int l = 0; l < LL; l++) {
        const float* blinL = b_lin + (size_t)l * THX;
        const float* bihL  = b_ih + (size_t)l * H3;
        const float* bhhL  = b_hh + (size_t)l * H3;
        const float* WTl   = p_WT + (size_t)l * HH * THX;
        const float* wiTl  = p_wiT + (size_t)l * HH * H3;
        const float* whTl  = p_whT + (size_t)l * HH * H3;

        for (int s = 0; s < SS; s++) {
            // Wh = h @ WT + b_lin   [N, T*H]
            sgemm_kernel<<<grid_wh, 256>>>(p_h, WTl, blinL, p_Wh, NN, THX, HH);
            // a = 0 ; a[dst] += Wh[src, etype]
            zero_kernel<<<(int)((a4 + 255) / 256), 256>>>(p_a, a4);
            scatter_kernel<<<scatter_blocks, 256>>>(p_Wh, src, dst, etype, p_a, E);
            // gx = a @ wiT + b_ih ; gh = h @ whT + b_hh  (gh overwrites Wh buffer)
            sgemm_kernel<<<grid_g, 256>>>(p_a, wiTl, bihL, p_gx, NN, H3, HH);
            sgemm_kernel<<<grid_g, 256>>>(p_h, whTl, bhhL, p_gh, NN, H3, HH);
            // GRU gates, in-place update of h
            gru_kernel<<<gru_blocks, 256>>>((const float4*)p_gx, (const float4*)p_gh,
                                            (float4*)p_h, (int)a4);
        }
    }

    // pooled mean + FC
    zero_kernel<<<1, 64>>>(p_pooled, HH / 4);
    pool_kernel<<<256, HH>>>(p_h, p_pooled, NN);
    fc_kernel<<<CC, 32>>>(p_pooled, fc_w, fc_b, out, 1.0f / (float)NN);
}

// round 4
// speedup vs baseline: 1.8039x; 1.8039x over previous
#include <cuda_runtime.h>
#include <cuda_bf16.h>
#include <math.h>
#include <stdint.h>

// Problem constants (fixed by the reference)
#define NN 50000
#define HH 256
#define TT 4
#define LL 2
#define SS 3
#define CC 3
#define H3 (3 * HH)
#define THX (TT * HH)   // 1024
#define KK HH           // GEMM K dim = 256

// ---------------- fp32 scratch: ONE device global, carved by offsets --------
#define OFF_H    ((size_t)0)                       // [NN*HH]   node state
#define OFF_WH   (OFF_H    + (size_t)NN * HH)      // [NN*THX]  per-etype transforms
#define OFF_A    (OFF_WH   + (size_t)NN * THX)     // [NN*HH]   aggregated messages
#define OFF_GX   (OFF_A    + (size_t)NN * HH)      // [NN*H3]   a @ w_ih.T
#define OFF_POOL (OFF_GX   + (size_t)NN * H3)      // [HH]
#define SCRATCH_FLOATS (OFF_POOL + HH)
// gh aliases the Wh buffer: Wh is dead after the scatter, gh produced after.
__device__ float s_scratch[SCRATCH_FLOATS];

// bf16 split weights (original [n][k] layout — no transpose needed!)
__device__ __nv_bfloat16 s_Whi[(size_t)LL * THX * HH];
__device__ __nv_bfloat16 s_Wlo[(size_t)LL * THX * HH];
__device__ __nv_bfloat16 s_wihi[(size_t)LL * H3 * HH];
__device__ __nv_bfloat16 s_wilo[(size_t)LL * H3 * HH];
__device__ __nv_bfloat16 s_whhi[(size_t)LL * H3 * HH];
__device__ __nv_bfloat16 s_whlo[(size_t)LL * H3 * HH];

// ---------------- generic helpers ----------------
__global__ void copy_kernel(const float* __restrict__ in, float* __restrict__ out, size_t n4) {
    size_t i = (size_t)blockIdx.x * blockDim.x + threadIdx.x;
    if (i < n4) ((float4*)out)[i] = ((const float4*)in)[i];
}

__global__ void zero_kernel(float* __restrict__ p, size_t n4) {
    size_t i = (size_t)blockIdx.x * blockDim.x + threadIdx.x;
    if (i < n4) ((float4*)p)[i] = make_float4(0.f, 0.f, 0.f, 0.f);
}

// fp32 -> bf16 (hi) + bf16 residual (lo)
__global__ void split_kernel(const float* __restrict__ w, __nv_bfloat16* __restrict__ hi,
                             __nv_bfloat16* __restrict__ lo, int n) {
    int i = blockIdx.x * blockDim.x + threadIdx.x;
    if (i >= n) return;
    float v = w[i];
    __nv_bfloat16 h = __float2bfloat16_rn(v);
    hi[i] = h;
    lo[i] = __float2bfloat16_rn(v - __bfloat162float(h));
}

// ---------------- bf16x3 tensor-core GEMM ----------------
// C[M,Nc] = A[M,K] @ B^T (B is [Nc,K] bf16 hi/lo) + bias[Nc]
// CTA: 128x128 tile, 256 threads (8 warps, 2x4), warp tile 64x32,
// mma.sync m16n8k16 bf16, 3-term split (hi*hi + hi*lo + lo*hi).
#define GBM 128
#define GBN 128
#define GBK 32
#define SROW 20   // smem row stride in uint32 (16 data + 4 pad) — conflict-free

__device__ __forceinline__ void mma16816(float* c, const uint32_t* a, const uint32_t* b) {
    asm volatile(
        "mma.sync.aligned.m16n8k16.row.col.f32.bf16.bf16.f32 "
        "{%0,%1,%2,%3}, {%4,%5,%6,%7}, {%8,%9}, {%0,%1,%2,%3};"
        : "+f"(c[0]), "+f"(c[1]), "+f"(c[2]), "+f"(c[3])
        : "r"(a[0]), "r"(a[1]), "r"(a[2]), "r"(a[3]), "r"(b[0]), "r"(b[1]));
}

__device__ __forceinline__ uint32_t pack_hi2(float x, float y) {
    __nv_bfloat162 p;
    p.x = __float2bfloat16_rn(x);
    p.y = __float2bfloat16_rn(y);
    return *reinterpret_cast<uint32_t*>(&p);
}
__device__ __forceinline__ uint32_t pack_lo2(float x, float y, uint32_t hp) {
    __nv_bfloat162 h = *reinterpret_cast<__nv_bfloat162*>(&hp);
    __nv_bfloat162 p;
    p.x = __float2bfloat16_rn(x - __bfloat162float(h.x));
    p.y = __float2bfloat16_rn(y - __bfloat162float(h.y));
    return *reinterpret_cast<uint32_t*>(&p);
}

__global__ __launch_bounds__(256)
void mma_gemm_kernel(const float* __restrict__ A,
                     const __nv_bfloat16* __restrict__ Bhi,
                     const __nv_bfloat16* __restrict__ Blo,
                     const float* __restrict__ bias, float* __restrict__ C,
                     int M, int Nc) {
    __shared__ uint32_t Ash[GBM][SROW];
    __shared__ uint32_t Asl[GBM][SROW];
    __shared__ uint32_t Bsh[GBN][SROW];
    __shared__ uint32_t Bsl[GBN][SROW];

    const int tid = threadIdx.x;
    const int lane = tid & 31;
    const int wid = tid >> 5;
    const int wm = (wid >> 2) * 64;       // warp m offset (0 or 64)
    const int wn = (wid & 3) * 32;        // warp n offset
    const int g = lane >> 2;              // group id 0..7
    const int t = lane & 3;               // thread in group

    const int blockRow = blockIdx.y * GBM;
    const int blockCol = blockIdx.x * GBN;

    const uint32_t* B32h = (const uint32_t*)Bhi;
    const uint32_t* B32l = (const uint32_t*)Blo;
    const int Kw = KK / 2;                // B row stride in uint32

    float acc[4][4][4];
#pragma unroll
    for (int mi = 0; mi < 4; mi++)
#pragma unroll
        for (int ni = 0; ni < 4; ni++)
#pragma unroll
            for (int r = 0; r < 4; r++) acc[mi][ni][r] = 0.f;

    // staging registers
    float4 areg[4];
    uint4 bhr[2], blr[2];

    // A tile: 128 rows x 32 fp32 = 1024 float4, 4 per thread
    // B tile: 128 rows x 16 uint32 = 512 uint4, 2 per thread (per hi/lo)
    auto load_stage = [&](int k0) {
#pragma unroll
        for (int i = 0; i < 4; i++) {
            int lin = tid + 256 * i;
            int row = lin >> 3;           // 8 float4 per row
            int c4 = lin & 7;
            int gm = blockRow + row;
            areg[i] = (gm < M) ? *(const float4*)&A[(size_t)gm * KK + k0 + c4 * 4]
                               : make_float4(0.f, 0.f, 0.f, 0.f);
        }
#pragma unroll
        for (int i = 0; i < 2; i++) {
            int lin = tid + 256 * i;
            int row = lin >> 2;           // 4 uint4 per row
            int ch = lin & 3;
            size_t gi = (size_t)(blockCol + row) * Kw + (k0 >> 1) + ch * 4;
            bhr[i] = *(const uint4*)&B32h[gi];
            blr[i] = *(const uint4*)&B32l[gi];
        }
    };

    auto store_stage = [&]() {
#pragma unroll
        for (int i = 0; i < 4; i++) {
            int lin = tid + 256 * i;
            int row = lin >> 3;
            int c4 = lin & 7;
            float4 v = areg[i];
            uint32_t h0 = pack_hi2(v.x, v.y);
            uint32_t h1 = pack_hi2(v.z, v.w);
            Ash[row][c4 * 2 + 0] = h0;
            Ash[row][c4 * 2 + 1] = h1;
            Asl[row][c4 * 2 + 0] = pack_lo2(v.x, v.y, h0);
            Asl[row][c4 * 2 + 1] = pack_lo2(v.z, v.w, h1);
        }
#pragma unroll
        for (int i = 0; i < 2; i++) {
            int lin = tid + 256 * i;
            int row = lin >> 2;
            int ch = lin & 3;
            *(uint4*)&Bsh[row][ch * 4] = bhr[i];
            *(uint4*)&Bsl[row][ch * 4] = blr[i];
        }
    };

    load_stage(0);
    const int nStages = KK / GBK;         // 8
    for (int s = 0; s < nStages; s++) {
        store_stage();
        __syncthreads();
        if (s + 1 < nStages) load_stage((s + 1) * GBK);

#pragma unroll
        for (int ks = 0; ks < 2; ks++) {  // two k16 steps per GBK=32
            const int base = ks * 8;
            uint32_t ah[4][4], al[4][4], bh_[4][2], bl_[4][2];
#pragma unroll
            for (int mi = 0; mi < 4; mi++) {
                int r0 = wm + mi * 16 + g;
                ah[mi][0] = Ash[r0][base + t];
                ah[mi][1] = Ash[r0 + 8][base + t];
                ah[mi][2] = Ash[r0][base + t + 4];
                ah[mi][3] = Ash[r0 + 8][base + t + 4];
                al[mi][0] = Asl[r0][base + t];
                al[mi][1] = Asl[r0 + 8][base + t];
                al[mi][2] = Asl[r0][base + t + 4];
                al[mi][3] = Asl[r0 + 8][base + t + 4];
            }
#pragma unroll
            for (int ni = 0; ni < 4; ni++) {
                int n0 = wn + ni * 8 + g;
                bh_[ni][0] = Bsh[n0][base + t];
                bh_[ni][1] = Bsh[n0][base + t + 4];
                bl_[ni][0] = Bsl[n0][base + t];
                bl_[ni][1] = Bsl[n0][base + t + 4];
            }
#pragma unroll
            for (int mi = 0; mi < 4; mi++)
#pragma unroll
                for (int ni = 0; ni < 4; ni++) {
                    mma16816(acc[mi][ni], ah[mi], bh_[ni]);
                    mma16816(acc[mi][ni], ah[mi], bl_[ni]);
                    mma16816(acc[mi][ni], al[mi], bh_[ni]);
                }
        }
        __syncthreads();
    }

    // epilogue: bias + store (c0,c1 = row g cols 2t,2t+1; c2,c3 = row g+8)
#pragma unroll
    for (int mi = 0; mi < 4; mi++) {
        int r0 = blockRow + wm + mi * 16 + g;
        int r1 = r0 + 8;
#pragma unroll
        for (int ni = 0; ni < 4; ni++) {
            int col = blockCol + wn + ni * 8 + t * 2;
            float b0 = bias[col], b1 = bias[col + 1];
            if (r0 < M) {
                float2 v = make_float2(acc[mi][ni][0] + b0, acc[mi][ni][1] + b1);
                *(float2*)&C[(size_t)r0 * Nc + col] = v;
            }
            if (r1 < M) {
                float2 v = make_float2(acc[mi][ni][2] + b0, acc[mi][ni][3] + b1);
                *(float2*)&C[(size_t)r1 * Nc + col] = v;
            }
        }
    }
}

// ---------------- edge scatter: a[dst] += Wh[src, etype] ----------------
__global__ void scatter_kernel(const float* __restrict__ Wh,
                               const int* __restrict__ src,
                               const int* __restrict__ dst,
                               const int* __restrict__ et,
                               float* __restrict__ a, int E) {
    int gwarp = (int)(((size_t)blockIdx.x * blockDim.x + threadIdx.x) >> 5);
    int lane = threadIdx.x & 31;
    if (gwarp >= E) return;
    int s = __ldg(&src[gwarp]);
    int d = __ldg(&dst[gwarp]);
    int t = __ldg(&et[gwarp]);
    const float4* sp = (const float4*)(Wh + (size_t)s * THX + (size_t)t * HH);
    float4* dp = (float4*)(a + (size_t)d * HH);
#pragma unroll
    for (int i = 0; i < 2; i++) {
        float4 v = sp[lane + 32 * i];
        asm volatile("red.global.add.v4.f32 [%0], {%1,%2,%3,%4};"
                     :: "l"(dp + lane + 32 * i), "f"(v.x), "f"(v.y), "f"(v.z), "f"(v.w)
                     : "memory");
    }
}

// ---------------- GRU gates (elementwise, float4-vectorized) ----------------
__global__ void gru_kernel(const float4* __restrict__ gx, const float4* __restrict__ gh,
                           float4* __restrict__ h, int total4) {
    int idx = blockIdx.x * blockDim.x + threadIdx.x;
    if (idx >= total4) return;
    int n = idx >> 6;        // H/4 = 64 float4 per row
    int k = idx & 63;
    const float4* gxr = gx + (size_t)n * 192;  // 768/4
    const float4* ghr = gh + (size_t)n * 192;
    float4 xr = gxr[k], xz = gxr[64 + k], xn = gxr[128 + k];
    float4 hr = ghr[k], hz = ghr[64 + k], hn = ghr[128 + k];
    float4 hv = h[idx];
    float4 out;
#define GRU1(c)                                                       \
    {                                                                 \
        float r = 1.f / (1.f + expf(-(xr.c + hr.c)));                 \
        float z = 1.f / (1.f + expf(-(xz.c + hz.c)));                 \
        float nng = tanhf(xn.c + r * hn.c);                           \
        out.c = (1.f - z) * nng + z * hv.c;                           \
    }
    GRU1(x) GRU1(y) GRU1(z) GRU1(w)
#undef GRU1
    h[idx] = out;
}

// ---------------- pooling + FC ----------------
__global__ void pool_kernel(const float* __restrict__ h, float* __restrict__ pooled, int n) {
    int k = threadIdx.x;  // 256
    float acc = 0.f;
    for (int r = blockIdx.x; r < n; r += gridDim.x)
        acc += h[(size_t)r * HH + k];
    atomicAdd(&pooled[k], acc);
}

__global__ void fc_kernel(const float* __restrict__ pooled, const float* __restrict__ fc_w,
                          const float* __restrict__ fc_b, float* __restrict__ out, float invN) {
    int c = blockIdx.x;
    int lane = threadIdx.x;
    float acc = 0.f;
    for (int k = lane; k < HH; k += 32) acc += pooled[k] * fc_w[c * HH + k];
#pragma unroll
    for (int o = 16; o; o >>= 1) acc += __shfl_xor_sync(0xffffffffu, acc, o);
    if (lane == 0) out[c] = acc * invN + fc_b[c];
}

// ---------------- host orchestration ----------------
extern "C" void kernel_launch(void* const* d_in, const int* in_sizes, int n_in,
                              void* d_out, int out_size) {
    const float* x      = (const float*)d_in[0];
    const int*   src    = (const int*)d_in[1];
    const int*   dst    = (const int*)d_in[2];
    const int*   etype  = (const int*)d_in[3];
    const float* W_lin  = (const float*)d_in[4];   // [L,T,H,H] == [L][THX][K]
    const float* b_lin  = (const float*)d_in[5];   // [L,T,H]
    const float* w_ih   = (const float*)d_in[6];   // [L,3H,H] == [L][H3][K]
    const float* w_hh   = (const float*)d_in[7];   // [L,3H,H]
    const float* b_ih   = (const float*)d_in[8];   // [L,3H]
    const float* b_hh   = (const float*)d_in[9];   // [L,3H]
    const float* fc_w   = (const float*)d_in[10];  // [C,H]
    const float* fc_b   = (const float*)d_in[11];  // [C]
    float* out = (float*)d_out;

    const int E = in_sizes[1];

    float* base = nullptr;
    cudaGetSymbolAddress((void**)&base, s_scratch);
    float* p_h      = base + OFF_H;
    float* p_Wh     = base + OFF_WH;
    float* p_gh     = base + OFF_WH;   // alias: Wh dead after scatter
    float* p_a      = base + OFF_A;
    float* p_gx     = base + OFF_GX;
    float* p_pooled = base + OFF_POOL;

    __nv_bfloat16 *p_Whi, *p_Wlo, *p_wihi, *p_wilo, *p_whhi, *p_whlo;
    cudaGetSymbolAddress((void**)&p_Whi, s_Whi);
    cudaGetSymbolAddress((void**)&p_Wlo, s_Wlo);
    cudaGetSymbolAddress((void**)&p_wihi, s_wihi);
    cudaGetSymbolAddress((void**)&p_wilo, s_wilo);
    cudaGetSymbolAddress((void**)&p_whhi, s_whhi);
    cudaGetSymbolAddress((void**)&p_whlo, s_whlo);

    // ---- weight splits (once per launch; original [n][k] layout kept) ----
    {
        int nW = LL * THX * HH;
        int nG = LL * H3 * HH;
        split_kernel<<<(nW + 255) / 256, 256>>>(W_lin, p_Whi, p_Wlo, nW);
        split_kernel<<<(nG + 255) / 256, 256>>>(w_ih, p_wihi, p_wilo, nG);
        split_kernel<<<(nG + 255) / 256, 256>>>(w_hh, p_whhi, p_whlo, nG);
    }

    // ---- h = x ----
    size_t n4 = (size_t)NN * HH / 4;
    copy_kernel<<<(int)((n4 + 255) / 256), 256>>>(x, p_h, n4);

    dim3 grid_wh(THX / GBN, (NN + GBM - 1) / GBM);   // (8, 391)
    dim3 grid_g(H3 / GBN, (NN + GBM - 1) / GBM);     // (6, 391)
    int scatter_blocks = (int)(((size_t)E * 32 + 255) / 256);
    int gru_blocks = (int)((n4 + 255) / 256);

    for (int l = 0; l < LL; l++) {
        const float* blinL = b_lin + (size_t)l * THX;
        const float* bihL  = b_ih + (size_t)l * H3;
        const float* bhhL  = b_hh + (size_t)l * H3;
        const __nv_bfloat16* Whl  = p_Whi + (size_t)l * THX * HH;
        const __nv_bfloat16* Wll  = p_Wlo + (size_t)l * THX * HH;
        const __nv_bfloat16* wihl = p_wihi + (size_t)l * H3 * HH;
        const __nv_bfloat16* will = p_wilo + (size_t)l * H3 * HH;
        const __nv_bfloat16* whhl = p_whhi + (size_t)l * H3 * HH;
        const __nv_bfloat16* whll = p_whlo + (size_t)l * H3 * HH;

        for (int s = 0; s < SS; s++) {
            // Wh = h @ W^T + b_lin   [N, T*H]
            mma_gemm_kernel<<<grid_wh, 256>>>(p_h, Whl, Wll, blinL, p_Wh, NN, THX);
            // a = 0 ; a[dst] += Wh[src, etype]
            zero_kernel<<<(int)((n4 + 255) / 256), 256>>>(p_a, n4);
            scatter_kernel<<<scatter_blocks, 256>>>(p_Wh, src, dst, etype, p_a, E);
            // gx = a @ w_ih^T + b_ih ; gh = h @ w_hh^T + b_hh (gh overwrites Wh)
            mma_gemm_kernel<<<grid_g, 256>>>(p_a, wihl, will, bihL, p_gx, NN, H3);
            mma_gemm_kernel<<<grid_g, 256>>>(p_h, whhl, whll, bhhL, p_gh, NN, H3);
            // GRU gates, in-place update of h
            gru_kernel<<<gru_blocks, 256>>>((const float4*)p_gx, (const float4*)p_gh,
                                            (float4*)p_h, (int)n4);
        }
    }

    // pooled mean + FC
    zero_kernel<<<1, 64>>>(p_pooled, HH / 4);
    pool_kernel<<<256, HH>>>(p_h, p_pooled, NN);
    fc_kernel<<<CC, 32>>>(p_pooled, fc_w, fc_b, out, 1.0f / (float)NN);
}